// round 9
// baseline (speedup 1.0000x reference)
#include <cuda_runtime.h>

#define N_NODES  50000
#define SLOTS    96
#define HID      128
#define IN_DIM   64
#define OUT_DIM  10
#define N_GRAPHS 64

// ---------------- scratch (device globals; referenced ONLY in device code) ---
// +8 rows: row N_NODES is a permanent zero row used as gather padding target.
__device__ int   g_cnt_i[N_NODES];                      // in-degree (excl self)
__device__ int   g_slots[(size_t)N_NODES * SLOTS];      // src ids bucketed by dst
__device__ float g_dinv[N_NODES];
__device__ float g_xs [(size_t)(N_NODES + 8) * IN_DIM]; // dinv * x  (+zero row)
__device__ float g_y1 [(size_t)N_NODES * IN_DIM];       // dinv*(A+I)*xs
__device__ float g_h1s[(size_t)(N_NODES + 8) * HID];    // dinv*relu(...) (+zero row)
__device__ float g_y2 [(size_t)N_NODES * HID];
__device__ float g_pool[N_GRAPHS * HID];
__device__ float g_cnt[N_GRAPHS];

// packed fp32x2 FMA (sm_103a dual fp32 pipe; only reachable via PTX)
#define FMA2(d, a, b) \
    asm("fma.rn.f32x2 %0, %1, %2, %0;" : "+l"(d) : "l"(a), "l"(b))

// ---------------- init --------------------------------------------------------
__global__ void init_kernel() {
    int i = blockIdx.x * blockDim.x + threadIdx.x;
    if (i < N_NODES) g_cnt_i[i] = 0;
    if (i < N_GRAPHS * HID) g_pool[i] = 0.0f;
    if (i < N_GRAPHS) g_cnt[i] = 0.0f;
    if (i < 8 * IN_DIM) g_xs[(size_t)N_NODES * IN_DIM + i] = 0.0f;
    if (i < 8 * HID)    g_h1s[(size_t)N_NODES * HID + i] = 0.0f;
}

// one fused pass: degree count + bucket fill
__global__ void build_kernel(const int* __restrict__ ei, int E) {
    int i = blockIdx.x * blockDim.x + threadIdx.x;
    if (i < E) {
        int s = ei[i];
        int d = ei[E + i];
        int p = atomicAdd(&g_cnt_i[d], 1);
        if (p < SLOTS) g_slots[(size_t)d * SLOTS + p] = s;
    }
}

// per node: dinv, graph count, pad bucket to multiple of 4 with zero-row index
__global__ void prep_node_kernel(const int* __restrict__ batch) {
    int i = blockIdx.x * blockDim.x + threadIdx.x;
    if (i >= N_NODES) return;
    int c = min(g_cnt_i[i], SLOTS);
    g_dinv[i] = rsqrtf((float)g_cnt_i[i] + 1.0f);
    atomicAdd(&g_cnt[__ldg(batch + i)], 1.0f);
    int cp = (c + 3) & ~3;
    int* bucket = g_slots + (size_t)i * SLOTS;
    for (int p = c; p < cp; p++) bucket[p] = N_NODES;   // zero row
}

// g_xs = dinv * x (coalesced float4 pass)
__global__ void scale_x_kernel(const float* __restrict__ x) {
    int idx = blockIdx.x * blockDim.x + threadIdx.x;   // float4 index
    if (idx >= N_NODES * (IN_DIM / 4)) return;
    int n = idx >> 4;
    float dv = g_dinv[n];
    float4 v = ((const float4*)x)[idx];
    v.x *= dv; v.y *= dv; v.z *= dv; v.w *= dv;
    ((float4*)g_xs)[idx] = v;
}

// ---------------- layer-1 aggregation: y1[n] = dinv[n]*(xs[n] + sum xs[s]) ---
// 2 nodes per warp, 16 lanes per node, float4 per lane, int4 broadcast indices.
__global__ void __launch_bounds__(256) agg1_kernel() {
    int gid = blockIdx.x * blockDim.x + threadIdx.x;
    int node = gid >> 4;                 // 16 lanes per node
    if (node >= N_NODES) return;
    int hl = threadIdx.x & 15;           // lane within node group

    const float* __restrict__ xs = g_xs;
    float4 a0 = *(const float4*)(xs + (size_t)node * IN_DIM + hl * 4);
    float4 a1 = make_float4(0.f, 0.f, 0.f, 0.f);

    int cnt = min(g_cnt_i[node], SLOTS);
    int cnt_p = (cnt + 3) & ~3;
    const int* bucket = g_slots + (size_t)node * SLOTS;

#pragma unroll 2
    for (int b = 0; b < cnt_p; b += 4) {
        int4 q = *(const int4*)(bucket + b);     // broadcast within group
        float4 v0 = *(const float4*)(xs + (size_t)q.x * IN_DIM + hl * 4);
        float4 v1 = *(const float4*)(xs + (size_t)q.y * IN_DIM + hl * 4);
        float4 v2 = *(const float4*)(xs + (size_t)q.z * IN_DIM + hl * 4);
        float4 v3 = *(const float4*)(xs + (size_t)q.w * IN_DIM + hl * 4);
        a0.x += v0.x + v1.x; a0.y += v0.y + v1.y;
        a0.z += v0.z + v1.z; a0.w += v0.w + v1.w;
        a1.x += v2.x + v3.x; a1.y += v2.y + v3.y;
        a1.z += v2.z + v3.z; a1.w += v2.w + v3.w;
    }
    float dv = g_dinv[node];
    float4 r;
    r.x = dv * (a0.x + a1.x); r.y = dv * (a0.y + a1.y);
    r.z = dv * (a0.z + a1.z); r.w = dv * (a0.w + a1.w);
    *(float4*)(g_y1 + (size_t)node * IN_DIM + hl * 4) = r;
}

// ---------------- layer-2 aggregation: y2[n] = dinv[n]*(h1s[n] + sum h1s[s]) -
// 1 node per warp, 32 lanes, float4 per lane, int4 broadcast indices.
__global__ void __launch_bounds__(256) agg2_kernel() {
    int warp = (blockIdx.x * blockDim.x + threadIdx.x) >> 5;
    if (warp >= N_NODES) return;
    int lane = threadIdx.x & 31;

    const float* __restrict__ hs = g_h1s;
    float4 a0 = *(const float4*)(hs + (size_t)warp * HID + lane * 4);
    float4 a1 = make_float4(0.f, 0.f, 0.f, 0.f);

    int cnt = min(g_cnt_i[warp], SLOTS);
    int cnt_p = (cnt + 3) & ~3;
    const int* bucket = g_slots + (size_t)warp * SLOTS;

#pragma unroll 2
    for (int b = 0; b < cnt_p; b += 4) {
        int4 q = *(const int4*)(bucket + b);     // broadcast across warp
        float4 v0 = *(const float4*)(hs + (size_t)q.x * HID + lane * 4);
        float4 v1 = *(const float4*)(hs + (size_t)q.y * HID + lane * 4);
        float4 v2 = *(const float4*)(hs + (size_t)q.z * HID + lane * 4);
        float4 v3 = *(const float4*)(hs + (size_t)q.w * HID + lane * 4);
        a0.x += v0.x + v1.x; a0.y += v0.y + v1.y;
        a0.z += v0.z + v1.z; a0.w += v0.w + v1.w;
        a1.x += v2.x + v3.x; a1.y += v2.y + v3.y;
        a1.z += v2.z + v3.z; a1.w += v2.w + v3.w;
    }
    float dv = g_dinv[warp];
    float4 r;
    r.x = dv * (a0.x + a1.x); r.y = dv * (a0.y + a1.y);
    r.z = dv * (a0.z + a1.z); r.w = dv * (a0.w + a1.w);
    *(float4*)(g_y2 + (size_t)warp * HID + lane * 4) = r;
}

// ---------------- GEMM: 64x128 tile, 256 threads, 8x4 per thread, f32x2 ------
// LAYER2=false: g_h1s[row] = dinv[row] * relu(g_y1 W^T + b)   (K=64)
// LAYER2=true : g_pool[batch[row]] += relu(g_y2 W^T + b)      (K=128)
template <bool LAYER2>
__global__ void __launch_bounds__(256) gemm_kernel(const float* __restrict__ W,
                                                   const float* __restrict__ bias,
                                                   const int* __restrict__ batch) {
    const int K = LAYER2 ? HID : IN_DIM;
    const float* __restrict__ Xin = LAYER2 ? g_y2 : g_y1;

    __shared__ float ws2[32][260];   // B duplicated: col c at [2c], [2c+1]
    __shared__ float xs[32][68];     // [k][row]

    int tid = threadIdx.x;
    int tr = tid >> 5;    // 0..7  row-group
    int tc = tid & 31;    // 0..31 col-group
    int row0 = blockIdx.x * 64;

    unsigned long long acc[4][4] = {};   // [row-pair][col]

    for (int kc = 0; kc < K; kc += 32) {
        for (int i = tid; i < 128 * 32; i += 256) {
            int c = i >> 5, k = i & 31;
            float v = W[c * K + kc + k];
            ws2[k][2 * c] = v;
            ws2[k][2 * c + 1] = v;
        }
        for (int i = tid; i < 64 * 32; i += 256) {
            int r = i >> 5, k = i & 31;
            int row = row0 + r;
            xs[k][r] = (row < N_NODES) ? Xin[(size_t)row * K + kc + k] : 0.0f;
        }
        __syncthreads();

#pragma unroll
        for (int k = 0; k < 32; k++) {
            ulonglong2 A0 = *(const ulonglong2*)&xs[k][tr * 8];
            ulonglong2 A1 = *(const ulonglong2*)&xs[k][tr * 8 + 4];
            ulonglong2 B0 = *(const ulonglong2*)&ws2[k][tc * 8];
            ulonglong2 B1 = *(const ulonglong2*)&ws2[k][tc * 8 + 4];
            FMA2(acc[0][0], A0.x, B0.x); FMA2(acc[0][1], A0.x, B0.y);
            FMA2(acc[0][2], A0.x, B1.x); FMA2(acc[0][3], A0.x, B1.y);
            FMA2(acc[1][0], A0.y, B0.x); FMA2(acc[1][1], A0.y, B0.y);
            FMA2(acc[1][2], A0.y, B1.x); FMA2(acc[1][3], A0.y, B1.y);
            FMA2(acc[2][0], A1.x, B0.x); FMA2(acc[2][1], A1.x, B0.y);
            FMA2(acc[2][2], A1.x, B1.x); FMA2(acc[2][3], A1.x, B1.y);
            FMA2(acc[3][0], A1.y, B0.x); FMA2(acc[3][1], A1.y, B0.y);
            FMA2(acc[3][2], A1.y, B1.x); FMA2(acc[3][3], A1.y, B1.y);
        }
        __syncthreads();
    }

    float4 bb = *(const float4*)&bias[tc * 4];
    float bbv[4] = {bb.x, bb.y, bb.z, bb.w};

#pragma unroll
    for (int p = 0; p < 4; p++) {
        int r0 = row0 + tr * 8 + 2 * p;
        int r1 = r0 + 1;
        float lo[4], hi[4];
#pragma unroll
        for (int q = 0; q < 4; q++) {
            asm("mov.b64 {%0, %1}, %2;" : "=f"(lo[q]), "=f"(hi[q]) : "l"(acc[p][q]));
            lo[q] = fmaxf(lo[q] + bbv[q], 0.0f);
            hi[q] = fmaxf(hi[q] + bbv[q], 0.0f);
        }
        if (!LAYER2) {
            if (r0 < N_NODES) {
                float dv = g_dinv[r0];
                float4 v = make_float4(lo[0] * dv, lo[1] * dv, lo[2] * dv, lo[3] * dv);
                *(float4*)&g_h1s[(size_t)r0 * HID + tc * 4] = v;
            }
            if (r1 < N_NODES) {
                float dv = g_dinv[r1];
                float4 v = make_float4(hi[0] * dv, hi[1] * dv, hi[2] * dv, hi[3] * dv);
                *(float4*)&g_h1s[(size_t)r1 * HID + tc * 4] = v;
            }
        } else {
            if (r0 < N_NODES) {
                float* dst = g_pool + (size_t)__ldg(batch + r0) * HID + tc * 4;
                asm volatile("red.global.add.v4.f32 [%0], {%1, %2, %3, %4};"
                             :: "l"(dst), "f"(lo[0]), "f"(lo[1]), "f"(lo[2]), "f"(lo[3])
                             : "memory");
            }
            if (r1 < N_NODES) {
                float* dst = g_pool + (size_t)__ldg(batch + r1) * HID + tc * 4;
                asm volatile("red.global.add.v4.f32 [%0], {%1, %2, %3, %4};"
                             :: "l"(dst), "f"(hi[0]), "f"(hi[1]), "f"(hi[2]), "f"(hi[3])
                             : "memory");
            }
        }
    }
}

// ---------------- final: out[g][o] = pooled[g] . fc_w[o] + fc_b[o] -----------
__global__ void final_kernel(const float* __restrict__ fcw,
                             const float* __restrict__ fcb,
                             float* __restrict__ out) {
    int g = blockIdx.x;
    int lane = threadIdx.x;
    float inv = 1.0f / fmaxf(g_cnt[g], 1.0f);
    float p[4];
#pragma unroll
    for (int j = 0; j < 4; j++) p[j] = g_pool[g * HID + j * 32 + lane] * inv;
#pragma unroll
    for (int o = 0; o < OUT_DIM; o++) {
        float s = 0.0f;
#pragma unroll
        for (int j = 0; j < 4; j++) s += p[j] * fcw[o * HID + j * 32 + lane];
#pragma unroll
        for (int off = 16; off; off >>= 1) s += __shfl_down_sync(0xFFFFFFFFu, s, off);
        if (lane == 0) out[g * OUT_DIM + o] = s + fcb[o];
    }
}

// ---------------- launch ------------------------------------------------------
extern "C" void kernel_launch(void* const* d_in, const int* in_sizes, int n_in,
                              void* d_out, int out_size) {
    const float* x     = (const float*)d_in[0];
    const int*   ei    = (const int*)  d_in[1];
    const int*   batch = (const int*)  d_in[2];
    const float* w1    = (const float*)d_in[3];
    const float* b1    = (const float*)d_in[4];
    const float* w2    = (const float*)d_in[5];
    const float* b2    = (const float*)d_in[6];
    const float* fcw   = (const float*)d_in[7];
    const float* fcb   = (const float*)d_in[8];
    float* out = (float*)d_out;
    int E = in_sizes[1] / 2;

    int nblk = (N_NODES + 255) / 256;
    int eblk = (E + 255) / 256;
    int agg1_blocks = (N_NODES * 16 + 255) / 256;  // 16 lanes per node
    int agg2_blocks = (N_NODES * 32 + 255) / 256;  // one warp per node
    int gemm_blocks = (N_NODES + 63) / 64;

    init_kernel<<<nblk, 256>>>();
    build_kernel<<<eblk, 256>>>(ei, E);
    prep_node_kernel<<<nblk, 256>>>(batch);
    scale_x_kernel<<<(N_NODES * 16 + 255) / 256, 256>>>(x);

    // layer 1
    agg1_kernel<<<agg1_blocks, 256>>>();
    gemm_kernel<false><<<gemm_blocks, 256>>>(w1, b1, nullptr);

    // layer 2
    agg2_kernel<<<agg2_blocks, 256>>>();
    gemm_kernel<true><<<gemm_blocks, 256>>>(w2, b2, batch);

    final_kernel<<<N_GRAPHS, 32>>>(fcw, fcb, out);
}

// round 10
// speedup vs baseline: 1.8975x; 1.8975x over previous
#include <cuda_runtime.h>
#include <cuda_fp16.h>

#define N_NODES  50000
#define SLOTS    96
#define HID      128
#define IN_DIM   64
#define OUT_DIM  10
#define N_GRAPHS 64

// ---------------- scratch (device globals; referenced ONLY in device code) ---
// row N_NODES (and +7 spare) is a permanent zero row used as gather padding.
__device__ int    g_cnt_i[N_NODES];
__device__ int    g_slots[(size_t)N_NODES * SLOTS];
__device__ float  g_dinv[N_NODES];
__device__ __half g_xsh[(size_t)(N_NODES + 8) * IN_DIM];  // dinv * x
__device__ __half g_y1h[(size_t)(N_NODES + 8) * IN_DIM];  // agg1 out / gemm1 in
__device__ __half g_h1h[(size_t)(N_NODES + 8) * HID];     // gemm1 out (dinv*relu)
__device__ __half g_y2h[(size_t)(N_NODES + 8) * HID];     // agg2 out / gemm2 in
__device__ __half g_h2h[(size_t)N_NODES * HID];           // gemm2 out (relu)
__device__ __half g_w1h[HID * IN_DIM];
__device__ __half g_w2h[HID * HID];
__device__ float  g_pool[N_GRAPHS * HID];
__device__ float  g_cnt[N_GRAPHS];

// ---------------- PTX helpers -------------------------------------------------
__device__ __forceinline__ unsigned s2u(const void* p) {
    unsigned a;
    asm("{ .reg .u64 t; cvta.to.shared.u64 t, %1; cvt.u32.u64 %0, t; }"
        : "=r"(a) : "l"(p));
    return a;
}

__device__ __forceinline__ void ldsm4(unsigned* r, unsigned addr) {
    asm volatile("ldmatrix.sync.aligned.m8n8.x4.shared.b16 {%0,%1,%2,%3}, [%4];"
                 : "=r"(r[0]), "=r"(r[1]), "=r"(r[2]), "=r"(r[3]) : "r"(addr));
}

__device__ __forceinline__ void mma16816(float* d, const unsigned* a,
                                         unsigned b0, unsigned b1) {
    asm volatile(
        "mma.sync.aligned.m16n8k16.row.col.f32.f16.f16.f32 "
        "{%0,%1,%2,%3}, {%4,%5,%6,%7}, {%8,%9}, {%0,%1,%2,%3};"
        : "+f"(d[0]), "+f"(d[1]), "+f"(d[2]), "+f"(d[3])
        : "r"(a[0]), "r"(a[1]), "r"(a[2]), "r"(a[3]), "r"(b0), "r"(b1));
}

__device__ __forceinline__ void acc_h4(float* a, const __half* p) {
    uint2 u = *(const uint2*)p;
    float2 f0 = __half22float2(*(__half2*)&u.x);
    float2 f1 = __half22float2(*(__half2*)&u.y);
    a[0] += f0.x; a[1] += f0.y; a[2] += f1.x; a[3] += f1.y;
}

// ---------------- init (+ weight conversion) ----------------------------------
__global__ void init_kernel(const float* __restrict__ w1,
                            const float* __restrict__ w2) {
    int i = blockIdx.x * blockDim.x + threadIdx.x;
    if (i < N_NODES) g_cnt_i[i] = 0;
    if (i < N_GRAPHS * HID) g_pool[i] = 0.0f;
    if (i < N_GRAPHS) g_cnt[i] = 0.0f;
    if (i < 8 * IN_DIM) g_xsh[(size_t)N_NODES * IN_DIM + i] = __float2half(0.0f);
    if (i < 8 * HID)    g_h1h[(size_t)N_NODES * HID + i] = __float2half(0.0f);
    if (i < HID * IN_DIM) g_w1h[i] = __float2half(w1[i]);
    if (i < HID * HID)    g_w2h[i] = __float2half(w2[i]);
}

// one fused pass: degree count + bucket fill
__global__ void build_kernel(const int* __restrict__ ei, int E) {
    int i = blockIdx.x * blockDim.x + threadIdx.x;
    if (i < E) {
        int s = ei[i];
        int d = ei[E + i];
        int p = atomicAdd(&g_cnt_i[d], 1);
        if (p < SLOTS) g_slots[(size_t)d * SLOTS + p] = s;
    }
}

// per node: dinv, graph counts, pad bucket to multiple of 4 with zero-row index
__global__ void prep_node_kernel(const int* __restrict__ batch) {
    int i = blockIdx.x * blockDim.x + threadIdx.x;
    if (i >= N_NODES) return;
    int c = min(g_cnt_i[i], SLOTS);
    g_dinv[i] = rsqrtf((float)g_cnt_i[i] + 1.0f);
    atomicAdd(&g_cnt[__ldg(batch + i)], 1.0f);
    int cp = (c + 3) & ~3;
    int* bucket = g_slots + (size_t)i * SLOTS;
    for (int p = c; p < cp; p++) bucket[p] = N_NODES;   // zero row
}

// g_xsh = half(dinv * x)
__global__ void scale_x_kernel(const float* __restrict__ x) {
    int idx = blockIdx.x * blockDim.x + threadIdx.x;   // float4 index
    if (idx >= N_NODES * (IN_DIM / 4)) return;
    int n = idx >> 4;
    float dv = g_dinv[n];
    float4 v = ((const float4*)x)[idx];
    uint2 o;
    *(__half2*)&o.x = __floats2half2_rn(v.x * dv, v.y * dv);
    *(__half2*)&o.y = __floats2half2_rn(v.z * dv, v.w * dv);
    *(uint2*)(g_xsh + (size_t)n * IN_DIM + (idx & 15) * 4) = o;
}

// ---------------- layer-1 aggregation (64-dim, 16 lanes/node) ----------------
__global__ void __launch_bounds__(256) agg1_kernel() {
    int gid = blockIdx.x * blockDim.x + threadIdx.x;
    int node = gid >> 4;
    if (node >= N_NODES) return;
    int hl = threadIdx.x & 15;

    float a[4] = {0.f, 0.f, 0.f, 0.f};
    acc_h4(a, g_xsh + (size_t)node * IN_DIM + hl * 4);   // self term

    int cnt = min(g_cnt_i[node], SLOTS);
    int cnt_p = (cnt + 3) & ~3;
    const int* bucket = g_slots + (size_t)node * SLOTS;

#pragma unroll 2
    for (int b = 0; b < cnt_p; b += 4) {
        int4 q = *(const int4*)(bucket + b);
        acc_h4(a, g_xsh + (size_t)q.x * IN_DIM + hl * 4);
        acc_h4(a, g_xsh + (size_t)q.y * IN_DIM + hl * 4);
        acc_h4(a, g_xsh + (size_t)q.z * IN_DIM + hl * 4);
        acc_h4(a, g_xsh + (size_t)q.w * IN_DIM + hl * 4);
    }
    float dv = g_dinv[node];
    uint2 o;
    *(__half2*)&o.x = __floats2half2_rn(a[0] * dv, a[1] * dv);
    *(__half2*)&o.y = __floats2half2_rn(a[2] * dv, a[3] * dv);
    *(uint2*)(g_y1h + (size_t)node * IN_DIM + hl * 4) = o;
}

// ---------------- layer-2 aggregation (128-dim, 32 lanes/node) ---------------
__global__ void __launch_bounds__(256) agg2_kernel() {
    int warp = (blockIdx.x * blockDim.x + threadIdx.x) >> 5;
    if (warp >= N_NODES) return;
    int lane = threadIdx.x & 31;

    float a[4] = {0.f, 0.f, 0.f, 0.f};
    acc_h4(a, g_h1h + (size_t)warp * HID + lane * 4);    // self term

    int cnt = min(g_cnt_i[warp], SLOTS);
    int cnt_p = (cnt + 3) & ~3;
    const int* bucket = g_slots + (size_t)warp * SLOTS;

#pragma unroll 2
    for (int b = 0; b < cnt_p; b += 4) {
        int4 q = *(const int4*)(bucket + b);
        acc_h4(a, g_h1h + (size_t)q.x * HID + lane * 4);
        acc_h4(a, g_h1h + (size_t)q.y * HID + lane * 4);
        acc_h4(a, g_h1h + (size_t)q.z * HID + lane * 4);
        acc_h4(a, g_h1h + (size_t)q.w * HID + lane * 4);
    }
    float dv = g_dinv[warp];
    uint2 o;
    *(__half2*)&o.x = __floats2half2_rn(a[0] * dv, a[1] * dv);
    *(__half2*)&o.y = __floats2half2_rn(a[2] * dv, a[3] * dv);
    *(uint2*)(g_y2h + (size_t)warp * HID + lane * 4) = o;
}

// ---------------- HMMA GEMM: 128x128 tile, 8 warps (2m x 4n), warp 64x32 -----
// LAYER2=false: g_h1h[row] = half(dinv[row] * relu(y1h W1^T + b))   (K=64)
// LAYER2=true : g_h2h[row] = half(relu(y2h W2^T + b))               (K=128)
template <int K, bool LAYER2>
__global__ void __launch_bounds__(256) hgemm_kernel(const float* __restrict__ bias) {
    const __half* __restrict__ Xin = LAYER2 ? g_y2h : g_y1h;
    const __half* __restrict__ Wh  = LAYER2 ? g_w2h : g_w1h;
    __half* __restrict__ Out       = LAYER2 ? g_h2h : g_h1h;

    __shared__ __half As[128][40];   // 40-half row stride (80B = 5x16B, odd units)
    __shared__ __half Bs[128][40];

    int tid = threadIdx.x;
    int warp = tid >> 5, l = tid & 31;
    int wm = warp >> 2, wn = warp & 3;
    int row0 = blockIdx.x * 128;

    float d[4][4][4];
#pragma unroll
    for (int i = 0; i < 4; i++)
#pragma unroll
        for (int j = 0; j < 4; j++)
#pragma unroll
            for (int r = 0; r < 4; r++) d[i][j][r] = 0.f;

    // ldmatrix lane address components
    int rowA = (l & 7) + ((l & 8) ? 8 : 0);
    int colA = (l & 16) ? 8 : 0;
    int rowB = (l & 7) + ((l & 16) ? 8 : 0);
    int colB = (l & 8) ? 8 : 0;
    unsigned a_base = s2u(&As[0][0]);
    unsigned b_base = s2u(&Bs[0][0]);

    for (int kc = 0; kc < K; kc += 32) {
#pragma unroll
        for (int j = 0; j < 2; j++) {
            int idx = tid + j * 256;
            int r = idx >> 2, ch = idx & 3;
            int gr = row0 + r;
            uint4 val = make_uint4(0, 0, 0, 0);
            if (gr < N_NODES)
                val = *(const uint4*)(Xin + (size_t)gr * K + kc + ch * 8);
            *(uint4*)&As[r][ch * 8] = val;
            *(uint4*)&Bs[r][ch * 8] = *(const uint4*)(Wh + r * K + kc + ch * 8);
        }
        __syncthreads();

#pragma unroll
        for (int k16 = 0; k16 < 32; k16 += 16) {
            unsigned bfrag[2][4];
#pragma unroll
            for (int jn = 0; jn < 2; jn++) {
                unsigned addr = b_base +
                    (unsigned)(((wn * 32 + jn * 16 + rowB) * 40 + k16 + colB) * 2);
                ldsm4(bfrag[jn], addr);
            }
#pragma unroll
            for (int im = 0; im < 4; im++) {
                unsigned afrag[4];
                unsigned addr = a_base +
                    (unsigned)(((wm * 64 + im * 16 + rowA) * 40 + k16 + colA) * 2);
                ldsm4(afrag, addr);
                mma16816(d[im][0], afrag, bfrag[0][0], bfrag[0][1]);
                mma16816(d[im][1], afrag, bfrag[0][2], bfrag[0][3]);
                mma16816(d[im][2], afrag, bfrag[1][0], bfrag[1][1]);
                mma16816(d[im][3], afrag, bfrag[1][2], bfrag[1][3]);
            }
        }
        __syncthreads();
    }

    // epilogue
#pragma unroll
    for (int im = 0; im < 4; im++) {
        int r_lo = row0 + wm * 64 + im * 16 + (l >> 2);
        int r_hi = r_lo + 8;
        float dvlo = 1.f, dvhi = 1.f;
        if (!LAYER2) {
            if (r_lo < N_NODES) dvlo = g_dinv[r_lo];
            if (r_hi < N_NODES) dvhi = g_dinv[r_hi];
        }
#pragma unroll
        for (int in = 0; in < 4; in++) {
            int n = wn * 32 + in * 8 + 2 * (l & 3);
            float2 bb = *(const float2*)(bias + n);
            float v0 = fmaxf(d[im][in][0] + bb.x, 0.f) * dvlo;
            float v1 = fmaxf(d[im][in][1] + bb.y, 0.f) * dvlo;
            float v2 = fmaxf(d[im][in][2] + bb.x, 0.f) * dvhi;
            float v3 = fmaxf(d[im][in][3] + bb.y, 0.f) * dvhi;
            if (r_lo < N_NODES)
                *(__half2*)(Out + (size_t)r_lo * HID + n) = __floats2half2_rn(v0, v1);
            if (r_hi < N_NODES)
                *(__half2*)(Out + (size_t)r_hi * HID + n) = __floats2half2_rn(v2, v3);
        }
    }
}

// ---------------- pooling: segmented sum of h2h rows by (sorted) batch -------
__global__ void pool_kernel(const int* __restrict__ batch) {
    int gw = (blockIdx.x * blockDim.x + threadIdx.x) >> 5;
    int n0 = gw * 32;
    if (n0 >= N_NODES) return;
    int lane = threadIdx.x & 31;
    int n1 = min(n0 + 32, N_NODES);

    float a[4] = {0.f, 0.f, 0.f, 0.f};
    int cur = __ldg(batch + n0);
    for (int n = n0; n < n1; n++) {
        int g = __ldg(batch + n);
        if (g != cur) {
            float* dst = g_pool + (size_t)cur * HID + lane * 4;
            asm volatile("red.global.add.v4.f32 [%0], {%1, %2, %3, %4};"
                         :: "l"(dst), "f"(a[0]), "f"(a[1]), "f"(a[2]), "f"(a[3])
                         : "memory");
            a[0] = a[1] = a[2] = a[3] = 0.f;
            cur = g;
        }
        acc_h4(a, g_h2h + (size_t)n * HID + lane * 4);
    }
    float* dst = g_pool + (size_t)cur * HID + lane * 4;
    asm volatile("red.global.add.v4.f32 [%0], {%1, %2, %3, %4};"
                 :: "l"(dst), "f"(a[0]), "f"(a[1]), "f"(a[2]), "f"(a[3])
                 : "memory");
}

// ---------------- final: out[g][o] = pooled[g]/cnt . fc_w[o] + fc_b[o] -------
__global__ void final_kernel(const float* __restrict__ fcw,
                             const float* __restrict__ fcb,
                             float* __restrict__ out) {
    int g = blockIdx.x;
    int lane = threadIdx.x;
    float inv = 1.0f / fmaxf(g_cnt[g], 1.0f);
    float p[4];
#pragma unroll
    for (int j = 0; j < 4; j++) p[j] = g_pool[g * HID + j * 32 + lane] * inv;
#pragma unroll
    for (int o = 0; o < OUT_DIM; o++) {
        float s = 0.0f;
#pragma unroll
        for (int j = 0; j < 4; j++) s += p[j] * fcw[o * HID + j * 32 + lane];
#pragma unroll
        for (int off = 16; off; off >>= 1) s += __shfl_down_sync(0xFFFFFFFFu, s, off);
        if (lane == 0) out[g * OUT_DIM + o] = s + fcb[o];
    }
}

// ---------------- launch ------------------------------------------------------
extern "C" void kernel_launch(void* const* d_in, const int* in_sizes, int n_in,
                              void* d_out, int out_size) {
    const float* x     = (const float*)d_in[0];
    const int*   ei    = (const int*)  d_in[1];
    const int*   batch = (const int*)  d_in[2];
    const float* w1    = (const float*)d_in[3];
    const float* b1    = (const float*)d_in[4];
    const float* w2    = (const float*)d_in[5];
    const float* b2    = (const float*)d_in[6];
    const float* fcw   = (const float*)d_in[7];
    const float* fcb   = (const float*)d_in[8];
    float* out = (float*)d_out;
    int E = in_sizes[1] / 2;

    int nblk = (N_NODES + 255) / 256;
    int eblk = (E + 255) / 256;
    int gemm_blocks = (N_NODES + 127) / 128;

    init_kernel<<<nblk, 256>>>(w1, w2);
    build_kernel<<<eblk, 256>>>(ei, E);
    prep_node_kernel<<<nblk, 256>>>(batch);
    scale_x_kernel<<<(N_NODES * 16 + 255) / 256, 256>>>(x);

    // layer 1
    agg1_kernel<<<(N_NODES * 16 + 255) / 256, 256>>>();
    hgemm_kernel<IN_DIM, false><<<gemm_blocks, 256>>>(b1);

    // layer 2
    agg2_kernel<<<(N_NODES * 32 + 255) / 256, 256>>>();
    hgemm_kernel<HID, true><<<gemm_blocks, 256>>>(b2);

    pool_kernel<<<nblk, 256>>>(batch);
    final_kernel<<<N_GRAPHS, 32>>>(fcw, fcb, out);
}